// round 13
// baseline (speedup 1.0000x reference)
#include <cuda_runtime.h>
#include <math.h>

// ---------------- problem constants ----------------
#define B      1024
#define S      10        // S0 == S1 == 10
#define P      128
#define E_DIM  32
#define H_NUM  8
#define O_DIM  32
#define D_DIM  256       // H*O
#define NMP    2
#define NCLS   8
#define KCAT   (2*D_DIM + E_DIM)   // 544

typedef unsigned long long u64;

// packed f32x2 helpers (sm_100+): two independent IEEE fp32 FMAs per instruction
__device__ __forceinline__ void fma2(u64& d, u64 a, u64 b) {
    asm("fma.rn.f32x2 %0,%1,%2,%0;" : "+l"(d) : "l"(a), "l"(b));
}
__device__ __forceinline__ float sum2(u64 v) {
    float a, b; asm("mov.b64 {%0,%1},%2;" : "=f"(a), "=f"(b) : "l"(v)); return a + b;
}

// ---------------- scratch (device globals; no allocation) ----------------
__device__ float f0_buf[B * P];                 // prep(ids)
__device__ float f1_buf[B * S * P];             // prep(n0)
__device__ float f2_buf[B * S * S * P];         // prep(n1)
__device__ float ed0_buf[B * S * E_DIM];
__device__ float g0_buf[B * D_DIM];
__device__ float g1_buf[B * S * D_DIM];
__device__ float ed0u_buf[B * S * E_DIM];
__device__ float gout_buf[NMP * B * D_DIM];

// transposed weights: layout [h][colpair cp][d2] float4 =
//   { W[2*d2][2cp], W[2*d2+1][2cp], W[2*d2][2cp+1], W[2*d2+1][2cp+1] }
// -> as ulonglong2: .x = (W[d][c],W[d+1][c])  .y = (W[d][c+1],W[d+1][c+1])
__device__ float4 wprept_buf[64 * 64];                 // Wprep: O=128 -> 64 cp, d2=64
__device__ float4 wn0t_buf[NMP * H_NUM * 16 * 64];     // [mp*8+h][16][64]
__device__ float4 ws0t_buf[NMP * H_NUM * 16 * 64];
__device__ float4 we0t_buf[NMP * H_NUM * 16 * 16];
__device__ float4 we1t_buf[NMP * H_NUM * 16 * 16];
__device__ float4 wn1t_buf[NMP * H_NUM * 16 * 128];
__device__ float4 ws1t_buf[NMP * H_NUM * 16 * 128];
__device__ float4 wedget_buf[NMP * 16 * 272];          // [mp][16][272]

// ---------------- weight transpose ----------------
// src: [HN][DIN][O]; dst: [HN][O/2][DIN/2] float4 as described above
__global__ void wtrans_kernel(float4* __restrict__ dst, const float* __restrict__ src,
                              int DIN, int O, int total) {
    int i = blockIdx.x * 256 + threadIdx.x;
    if (i >= total) return;
    int d2 = i % (DIN / 2);
    int cp = (i / (DIN / 2)) % (O / 2);
    int h  = i / ((DIN / 2) * (O / 2));
    const float* s = src + (long)h * DIN * O;
    int d = 2 * d2, c = 2 * cp;
    dst[i] = make_float4(s[d * O + c], s[(d + 1) * O + c],
                         s[d * O + c + 1], s[(d + 1) * O + c + 1]);
}

// ---------------- prep: out[i,:] = relu(feats[idx[i]] @ Wprep) ----------------
// block = 32 rows, 256 threads. thread -> (cp = t&63 -> cols 2cp,2cp+1; rg = t>>6 of 8 rows)
__global__ __launch_bounds__(256) void prep_kernel(
        float* __restrict__ out,
        const float* __restrict__ feats,
        const int* __restrict__ idx,
        const float4* __restrict__ Wt) {
    __shared__ __align__(16) float xs[32 * 128];   // 32 rows x 128 floats
    const int base = blockIdx.x * 32;
    const int t = threadIdx.x;
    const float4* feats4 = (const float4*)feats;
    for (int i = t; i < 32 * 32; i += 256) {
        int r = i >> 5, c = i & 31;
        int row = idx[base + r];
        ((float4*)xs)[r * 32 + c] = feats4[(long)row * 32 + c];
    }
    __syncthreads();
    const int cp = t & 63;
    const int rg = t >> 6;                      // 0..3, 8 rows each
    const ulonglong2* xs2 = (const ulonglong2*)xs;   // [row][32] d4-chunks
    const ulonglong2* w2  = (const ulonglong2*)(Wt + cp * 64);  // [d2]

    u64 acc[8][2];
#pragma unroll
    for (int r = 0; r < 8; r++) { acc[r][0] = 0ull; acc[r][1] = 0ull; }

#pragma unroll 4
    for (int d4 = 0; d4 < 32; d4++) {
        ulonglong2 wA = w2[2 * d4];       // d,d+1 : col c / col c+1
        ulonglong2 wB = w2[2 * d4 + 1];   // d+2,d+3
#pragma unroll
        for (int r = 0; r < 8; r++) {
            ulonglong2 xv = xs2[(rg * 8 + r) * 32 + d4];
            fma2(acc[r][0], xv.x, wA.x);
            fma2(acc[r][1], xv.x, wA.y);
            fma2(acc[r][0], xv.y, wB.x);
            fma2(acc[r][1], xv.y, wB.y);
        }
    }
#pragma unroll
    for (int r = 0; r < 8; r++) {
        int row = base + rg * 8 + r;
        out[(long)row * 128 + cp * 2 + 0] = fmaxf(sum2(acc[r][0]), 0.f);
        out[(long)row * 128 + cp * 2 + 1] = fmaxf(sum2(acc[r][1]), 0.f);
    }
}

// ---------------- edge embedding gather (for ed0 only) ----------------
__global__ void gather_edge_kernel(float* __restrict__ out,
                                   const float* __restrict__ emb,
                                   const int* __restrict__ eidx, int rows) {
    int i = blockIdx.x * blockDim.x + threadIdx.x;   // rows*8 float4 elems
    if (i < rows * 8) {
        int r = i >> 3, c = i & 7;
        ((float4*)out)[i] = ((const float4*)emb)[(long)eidx[r] * 8 + c];
    }
}

// ---------------- multi-head aggregation (packed f32x2, transposed weights) --------
// out[n, h*O+o] = relu( x@Ws + mean_s relu( neigh@Wn + ed@We ) )
// one block per node, 128 threads: h = t>>4, colpair cp = t&15 -> cols 2cp,2cp+1.
// weights: transposed [h][cp][d2] float4, read as ulonglong2 (2 per d4, contiguous).
template <int DIN>
__global__ __launch_bounds__(128) void agg_kernel(
        float* __restrict__ out,
        const float* __restrict__ x,
        const float* __restrict__ neigh,
        const float* __restrict__ ed,
        const int* __restrict__ eidx,
        const float* __restrict__ emb,
        const float4* __restrict__ Wst,
        const float4* __restrict__ Wnt,
        const float4* __restrict__ Wet) {
    constexpr int D4 = DIN / 4;
    __shared__ __align__(16) float xs[DIN];
    __shared__ __align__(16) float ns[S * DIN];
    __shared__ __align__(16) float es[S * E_DIM];
    const int n = blockIdx.x;
    const int t = threadIdx.x;

    for (int i = t; i < D4; i += 128)
        ((float4*)xs)[i] = ((const float4*)x)[(long)n * D4 + i];
    for (int i = t; i < S * D4; i += 128)
        ((float4*)ns)[i] = ((const float4*)neigh)[(long)n * S * D4 + i];
    if (eidx) {
        for (int i = t; i < S * (E_DIM / 4); i += 128) {
            int s = i >> 3, c = i & 7;
            ((float4*)es)[i] = ((const float4*)emb)[(long)eidx[n * S + s] * 8 + c];
        }
    } else {
        for (int i = t; i < S * (E_DIM / 4); i += 128)
            ((float4*)es)[i] = ((const float4*)ed)[(long)n * S * (E_DIM / 4) + i];
    }
    __syncthreads();

    const int h  = t >> 4;
    const int cp = t & 15;
    const ulonglong2* wn2 = (const ulonglong2*)(Wnt + (h * 16 + cp) * (DIN / 2));
    const ulonglong2* ws2 = (const ulonglong2*)(Wst + (h * 16 + cp) * (DIN / 2));
    const ulonglong2* we2 = (const ulonglong2*)(Wet + (h * 16 + cp) * (E_DIM / 2));

    const ulonglong2* xs2 = (const ulonglong2*)xs;
    const ulonglong2* ns2 = (const ulonglong2*)ns;
    const ulonglong2* es2 = (const ulonglong2*)es;

    u64 acc[S][2];
    u64 slf[2] = {0ull, 0ull};
#pragma unroll
    for (int s = 0; s < S; s++) { acc[s][0] = 0ull; acc[s][1] = 0ull; }

#pragma unroll 4
    for (int d4 = 0; d4 < D4; d4++) {
        ulonglong2 wnA = wn2[2 * d4];
        ulonglong2 wnB = wn2[2 * d4 + 1];
        ulonglong2 wsA = ws2[2 * d4];
        ulonglong2 wsB = ws2[2 * d4 + 1];
        ulonglong2 xv = xs2[d4];
        fma2(slf[0], xv.x, wsA.x);
        fma2(slf[1], xv.x, wsA.y);
        fma2(slf[0], xv.y, wsB.x);
        fma2(slf[1], xv.y, wsB.y);
#pragma unroll
        for (int s = 0; s < S; s++) {
            ulonglong2 nv = ns2[s * D4 + d4];
            fma2(acc[s][0], nv.x, wnA.x);
            fma2(acc[s][1], nv.x, wnA.y);
            fma2(acc[s][0], nv.y, wnB.x);
            fma2(acc[s][1], nv.y, wnB.y);
        }
    }
#pragma unroll
    for (int e4 = 0; e4 < E_DIM / 4; e4++) {
        ulonglong2 weA = we2[2 * e4];
        ulonglong2 weB = we2[2 * e4 + 1];
#pragma unroll
        for (int s = 0; s < S; s++) {
            ulonglong2 ev = es2[s * (E_DIM / 4) + e4];
            fma2(acc[s][0], ev.x, weA.x);
            fma2(acc[s][1], ev.x, weA.y);
            fma2(acc[s][0], ev.y, weB.x);
            fma2(acc[s][1], ev.y, weB.y);
        }
    }

    float m0 = 0.f, m1 = 0.f;
#pragma unroll
    for (int s = 0; s < S; s++) {
        m0 += fmaxf(sum2(acc[s][0]), 0.f);
        m1 += fmaxf(sum2(acc[s][1]), 0.f);
    }
    out[(long)n * D_DIM + h * O_DIM + cp * 2 + 0] = fmaxf(sum2(slf[0]) + m0 * (1.0f / S), 0.f);
    out[(long)n * D_DIM + h * O_DIM + cp * 2 + 1] = fmaxf(sum2(slf[1]) + m1 * (1.0f / S), 0.f);
}

// ---------------- edge update: relu(concat(src, g1, ed0) @ Wedge) ----------------
// block = 16 rows, 256 threads: cp = t&15 -> cols 2cp, row r = t>>4.
__global__ __launch_bounds__(256) void edge_update_kernel(
        float* __restrict__ ed0u,
        const float* __restrict__ g0,
        const float* __restrict__ g1,
        const float* __restrict__ ed0,
        const float4* __restrict__ Wt) {
    __shared__ __align__(16) float cs[16 * KCAT];
    const int base = blockIdx.x * 16;
    const int t = threadIdx.x;
    for (int i = t; i < 16 * KCAT; i += 256) {
        int r = i / KCAT, k = i % KCAT;
        int row = base + r;
        float v;
        if (k < D_DIM)           v = g0[(long)(row / S) * D_DIM + k];
        else if (k < 2 * D_DIM)  v = g1[(long)row * D_DIM + (k - D_DIM)];
        else                     v = ed0[(long)row * E_DIM + (k - 2 * D_DIM)];
        cs[r * KCAT + k] = v;
    }
    __syncthreads();
    const int cp = t & 15;
    const int r  = t >> 4;
    const ulonglong2* cs2 = (const ulonglong2*)(cs + r * KCAT);
    const ulonglong2* w2  = (const ulonglong2*)(Wt + cp * (KCAT / 2));
    u64 a0 = 0ull, a1 = 0ull;
#pragma unroll 4
    for (int k4 = 0; k4 < KCAT / 4; k4++) {
        ulonglong2 wA = w2[2 * k4];
        ulonglong2 wB = w2[2 * k4 + 1];
        ulonglong2 cv = cs2[k4];
        fma2(a0, cv.x, wA.x);
        fma2(a1, cv.x, wA.y);
        fma2(a0, cv.y, wB.x);
        fma2(a1, cv.y, wB.y);
    }
    ed0u[(long)(base + r) * E_DIM + cp * 2 + 0] = fmaxf(sum2(a0), 0.f);
    ed0u[(long)(base + r) * E_DIM + cp * 2 + 1] = fmaxf(sum2(a1), 0.f);
}

// ---------------- head: attention over metapaths + normalize + fc ----------------
__global__ void head_kernel(float* __restrict__ dout,
                            const float* __restrict__ gout,
                            const float* __restrict__ Wa,
                            const float* __restrict__ va,
                            const float* __restrict__ Wfc,
                            const float* __restrict__ bfc) {
    const int b = blockIdx.x, t = threadIdx.x;
    __shared__ float red[128];
    __shared__ float scores[2];
    __shared__ float sw[2];
    __shared__ float anrm[D_DIM];
    __shared__ float invn;
    const float* g0 = gout + (long)b * D_DIM;
    const float* g1 = gout + (long)B * D_DIM + (long)b * D_DIM;

    {   // scores[mp] = tanh(g @ Wa) . va
        int mp = t >> 6, j = t & 63;
        const float* g = mp ? g1 : g0;
        float hv = 0.f;
        for (int d = 0; d < D_DIM; d++) hv += g[d] * Wa[d * 64 + j];
        red[t] = tanhf(hv) * va[j];
    }
    __syncthreads();
    if (t < 2) {
        float s = 0.f;
        for (int j = 0; j < 64; j++) s += red[t * 64 + j];
        scores[t] = s;
    }
    __syncthreads();
    if (t == 0) {
        float m = fmaxf(scores[0], scores[1]);
        float e0 = expf(scores[0] - m), e1 = expf(scores[1] - m);
        float inv = 1.f / (e0 + e1);
        sw[0] = e0 * inv; sw[1] = e1 * inv;
        dout[B * NCLS + b]     = sw[0];   // weights[0, b]
        dout[B * NCLS + B + b] = sw[1];   // weights[1, b]
    }
    __syncthreads();
    float ss = 0.f;
    for (int d = t; d < D_DIM; d += 128) {
        float a = sw[0] * g0[d] + sw[1] * g1[d];
        anrm[d] = a;
        ss += a * a;
    }
    red[t] = ss;
    __syncthreads();
    for (int off = 64; off > 0; off >>= 1) {
        if (t < off) red[t] += red[t + off];
        __syncthreads();
    }
    if (t == 0) invn = 1.f / fmaxf(sqrtf(red[0]), 1e-12f);
    __syncthreads();
    {   // logits: 8 cols x 16 partial threads
        int c = t >> 4, p = t & 15;
        float acc = 0.f;
        for (int d = p; d < D_DIM; d += 16) acc += anrm[d] * invn * Wfc[d * NCLS + c];
        for (int off = 8; off > 0; off >>= 1) acc += __shfl_down_sync(0xffffffffu, acc, off, 16);
        if (p == 0) dout[b * NCLS + c] = acc + bfc[c];
    }
}

// ---------------- launch ----------------
extern "C" void kernel_launch(void* const* d_in, const int* in_sizes, int n_in,
                              void* d_out, int out_size) {
    const int*   ids      = (const int*)d_in[0];
    const int*   n0m[2]   = {(const int*)d_in[1], (const int*)d_in[5]};
    const int*   e0m[2]   = {(const int*)d_in[2], (const int*)d_in[6]};
    const int*   n1m[2]   = {(const int*)d_in[3], (const int*)d_in[7]};
    const int*   e1m[2]   = {(const int*)d_in[4], (const int*)d_in[8]};
    const float* feats    = (const float*)d_in[9];
    const float* embm[2]  = {(const float*)d_in[10], (const float*)d_in[11]};
    const float* Wprep    = (const float*)d_in[12];
    const float* Ws0      = (const float*)d_in[13];
    const float* Wn0      = (const float*)d_in[14];
    const float* We0      = (const float*)d_in[15];
    const float* Ws1      = (const float*)d_in[16];
    const float* Wn1      = (const float*)d_in[17];
    const float* We1      = (const float*)d_in[18];
    const float* Wedge0   = (const float*)d_in[19];
    const float* Wa       = (const float*)d_in[20];
    const float* va       = (const float*)d_in[21];
    const float* Wfc      = (const float*)d_in[22];
    const float* bfc      = (const float*)d_in[23];
    float*       dout     = (float*)d_out;

    float *f0, *f1, *f2, *ed0, *g0, *g1, *ed0u, *gout;
    float4 *wprept, *wn0t, *ws0t, *we0t, *we1t, *wn1t, *ws1t, *wedget;
    cudaGetSymbolAddress((void**)&f0,     f0_buf);
    cudaGetSymbolAddress((void**)&f1,     f1_buf);
    cudaGetSymbolAddress((void**)&f2,     f2_buf);
    cudaGetSymbolAddress((void**)&ed0,    ed0_buf);
    cudaGetSymbolAddress((void**)&g0,     g0_buf);
    cudaGetSymbolAddress((void**)&g1,     g1_buf);
    cudaGetSymbolAddress((void**)&ed0u,   ed0u_buf);
    cudaGetSymbolAddress((void**)&gout,   gout_buf);
    cudaGetSymbolAddress((void**)&wprept, wprept_buf);
    cudaGetSymbolAddress((void**)&wn0t,   wn0t_buf);
    cudaGetSymbolAddress((void**)&ws0t,   ws0t_buf);
    cudaGetSymbolAddress((void**)&we0t,   we0t_buf);
    cudaGetSymbolAddress((void**)&we1t,   we1t_buf);
    cudaGetSymbolAddress((void**)&wn1t,   wn1t_buf);
    cudaGetSymbolAddress((void**)&ws1t,   ws1t_buf);
    cudaGetSymbolAddress((void**)&wedget, wedget_buf);

    // ---- weight transposes (cheap, once per launch) ----
    {
        int n;
        n = 1 * 64 * 64;            wtrans_kernel<<<(n + 255) / 256, 256>>>(wprept, Wprep, 128, 128, n);
        n = 16 * 16 * 64;           wtrans_kernel<<<(n + 255) / 256, 256>>>(wn0t, Wn0, 128, 32, n);
        n = 16 * 16 * 64;           wtrans_kernel<<<(n + 255) / 256, 256>>>(ws0t, Ws0, 128, 32, n);
        n = 16 * 16 * 16;           wtrans_kernel<<<(n + 255) / 256, 256>>>(we0t, We0, 32, 32, n);
        n = 16 * 16 * 16;           wtrans_kernel<<<(n + 255) / 256, 256>>>(we1t, We1, 32, 32, n);
        n = 16 * 16 * 128;          wtrans_kernel<<<(n + 255) / 256, 256>>>(wn1t, Wn1, 256, 32, n);
        n = 16 * 16 * 128;          wtrans_kernel<<<(n + 255) / 256, 256>>>(ws1t, Ws1, 256, 32, n);
        n = 2 * 16 * 272;           wtrans_kernel<<<(n + 255) / 256, 256>>>(wedget, Wedge0, KCAT, 32, n);
    }

    // f0 = prep(ids): shared across metapaths (Wprep shared)
    prep_kernel<<<B / 32, 256>>>(f0, feats, ids, wprept);

    for (int mp = 0; mp < NMP; mp++) {
        const float4* wn0m = wn0t + mp * H_NUM * 16 * 64;
        const float4* ws0m = ws0t + mp * H_NUM * 16 * 64;
        const float4* we0m = we0t + mp * H_NUM * 16 * 16;
        const float4* we1m = we1t + mp * H_NUM * 16 * 16;
        const float4* wn1m = wn1t + mp * H_NUM * 16 * 128;
        const float4* ws1m = ws1t + mp * H_NUM * 16 * 128;
        const float4* wegm = wedget + mp * 16 * 272;

        prep_kernel<<<(B * S) / 32, 256>>>(f1, feats, n0m[mp], wprept);
        prep_kernel<<<(B * S * S) / 32, 256>>>(f2, feats, n1m[mp], wprept);

        gather_edge_kernel<<<(B * S * 8 + 255) / 256, 256>>>(ed0, embm[mp], e0m[mp], B * S);

        // g0: edges from ed0 buffer; g1: edges gathered in-kernel from emb (fused)
        agg_kernel<128><<<B, 128>>>(g0, f0, f1, ed0, (const int*)nullptr, (const float*)nullptr,
                                    ws0m, wn0m, we0m);
        agg_kernel<128><<<B * S, 128>>>(g1, f1, f2, (const float*)nullptr, e1m[mp], embm[mp],
                                        ws0m, wn0m, we0m);

        edge_update_kernel<<<(B * S) / 16, 256>>>(ed0u, g0, g1, ed0, wegm);

        agg_kernel<256><<<B, 128>>>(gout + (long)mp * B * D_DIM, g0, g1, ed0u,
                                    (const int*)nullptr, (const float*)nullptr,
                                    ws1m, wn1m, we1m);
    }

    head_kernel<<<B, 128>>>(dout, gout, Wa, va, Wfc, bfc);
}

// round 17
// speedup vs baseline: 2.9336x; 2.9336x over previous
#include <cuda_runtime.h>
#include <math.h>

// ---------------- problem constants ----------------
#define B      1024
#define S      10        // S0 == S1 == 10
#define P      128
#define E_DIM  32
#define H_NUM  8
#define O_DIM  32
#define D_DIM  256       // H*O
#define NMP    2
#define NCLS   8
#define KCAT   (2*D_DIM + E_DIM)   // 544

typedef unsigned long long u64;

// packed f32x2 helpers (sm_100+): two independent IEEE fp32 FMAs per instruction
__device__ __forceinline__ void fma2(u64& d, u64 a, u64 b) {
    asm("fma.rn.f32x2 %0,%1,%2,%0;" : "+l"(d) : "l"(a), "l"(b));
}
__device__ __forceinline__ float sum2(u64 v) {
    float a, b; asm("mov.b64 {%0,%1},%2;" : "=f"(a), "=f"(b) : "l"(v)); return a + b;
}

// ---------------- scratch (device globals; no allocation) ----------------
__device__ float f0_buf[B * P];                 // prep(ids)
__device__ float f1_buf[B * S * P];             // prep(n0)
__device__ float f2_buf[B * S * S * P];         // prep(n1)
__device__ float ed0_buf[B * S * E_DIM];
__device__ float g0_buf[B * D_DIM];
__device__ float g1_buf[B * S * D_DIM];
__device__ float ed0u_buf[B * S * E_DIM];
__device__ float gout_buf[NMP * B * D_DIM];

// pair-packed weights, WARP-COALESCED layout: float2[h][d2][col] where
//   elem = ( W[2*d2][col], W[2*d2+1][col] )  (read as u64 -> fma2 operand)
// At fixed d2 a warp's lanes read consecutive cols -> fully coalesced LDG.128.
__device__ float4 wprept_buf[64 * 64];                 // 8192 float2: [64 d2][128 col]
__device__ float4 wn0t_buf[NMP * H_NUM * 16 * 64];     // 32768 f2/mp-set: [16 h][64 d2][32 col]
__device__ float4 ws0t_buf[NMP * H_NUM * 16 * 64];
__device__ float4 we0t_buf[NMP * H_NUM * 16 * 16];     // [16 h][16 e2][32 col]
__device__ float4 we1t_buf[NMP * H_NUM * 16 * 16];
__device__ float4 wn1t_buf[NMP * H_NUM * 16 * 128];    // [16 h][128 d2][32 col]
__device__ float4 ws1t_buf[NMP * H_NUM * 16 * 128];
__device__ float4 wedget_buf[NMP * 16 * 272];          // [2 mp][272 k2][32 col]

// ---------------- weight pair-pack ----------------
// src: [HN][DIN][O]; dst float2: [HN][DIN/2][O], dst[i] = (W[2d2][col], W[2d2+1][col])
__global__ void wtrans_kernel(float2* __restrict__ dst, const float* __restrict__ src,
                              int DIN, int O, int total) {
    int i = blockIdx.x * 256 + threadIdx.x;
    if (i >= total) return;
    int col = i % O;
    int d2  = (i / O) % (DIN / 2);
    int h   = i / (O * (DIN / 2));
    const float* s = src + (long)h * DIN * O;
    dst[i] = make_float2(s[(2 * d2) * O + col], s[(2 * d2 + 1) * O + col]);
}

// ---------------- prep: out[i,:] = relu(feats[idx[i]] @ Wprep) ----------------
// block = 32 rows, 256 threads. thread -> (cp = t&63 -> cols 2cp,2cp+1; rg = t>>6 of 8 rows)
__global__ __launch_bounds__(256) void prep_kernel(
        float* __restrict__ out,
        const float* __restrict__ feats,
        const int* __restrict__ idx,
        const float2* __restrict__ Wt) {
    __shared__ __align__(16) float xs[32 * 128];   // 32 rows x 128 floats
    const int base = blockIdx.x * 32;
    const int t = threadIdx.x;
    const float4* feats4 = (const float4*)feats;
    for (int i = t; i < 32 * 32; i += 256) {
        int r = i >> 5, c = i & 31;
        int row = idx[base + r];
        ((float4*)xs)[r * 32 + c] = feats4[(long)row * 32 + c];
    }
    __syncthreads();
    const int cp = t & 63;
    const int rg = t >> 6;                      // 0..3, 8 rows each
    const ulonglong2* xs2 = (const ulonglong2*)xs;   // [row][32] d4-chunks
    const ulonglong2* w2  = (const ulonglong2*)Wt;   // [d2][64] col-pairs

    u64 acc[8][2];
#pragma unroll
    for (int r = 0; r < 8; r++) { acc[r][0] = 0ull; acc[r][1] = 0ull; }

#pragma unroll 4
    for (int d4 = 0; d4 < 32; d4++) {
        ulonglong2 wA = w2[(2 * d4)     * 64 + cp];   // d,d+1 : col c / col c+1
        ulonglong2 wB = w2[(2 * d4 + 1) * 64 + cp];   // d+2,d+3
#pragma unroll
        for (int r = 0; r < 8; r++) {
            ulonglong2 xv = xs2[(rg * 8 + r) * 32 + d4];
            fma2(acc[r][0], xv.x, wA.x);
            fma2(acc[r][1], xv.x, wA.y);
            fma2(acc[r][0], xv.y, wB.x);
            fma2(acc[r][1], xv.y, wB.y);
        }
    }
#pragma unroll
    for (int r = 0; r < 8; r++) {
        int row = base + rg * 8 + r;
        out[(long)row * 128 + cp * 2 + 0] = fmaxf(sum2(acc[r][0]), 0.f);
        out[(long)row * 128 + cp * 2 + 1] = fmaxf(sum2(acc[r][1]), 0.f);
    }
}

// ---------------- edge embedding gather (for ed0 only) ----------------
__global__ void gather_edge_kernel(float* __restrict__ out,
                                   const float* __restrict__ emb,
                                   const int* __restrict__ eidx, int rows) {
    int i = blockIdx.x * blockDim.x + threadIdx.x;   // rows*8 float4 elems
    if (i < rows * 8) {
        int r = i >> 3, c = i & 7;
        ((float4*)out)[i] = ((const float4*)emb)[(long)eidx[r] * 8 + c];
    }
}

// ---------------- multi-head aggregation (f32x2, coalesced packed weights) --------
// out[n, h*O+o] = relu( x@Ws + mean_s relu( neigh@Wn + ed@We ) )
// one block per node, 128 threads: h = t>>4, colpair cp = t&15 -> cols 2cp,2cp+1.
// weights float2 [h][d2][col]; per d2 warp lanes read consecutive cols (coalesced).
template <int DIN>
__global__ __launch_bounds__(128) void agg_kernel(
        float* __restrict__ out,
        const float* __restrict__ x,
        const float* __restrict__ neigh,
        const float* __restrict__ ed,
        const int* __restrict__ eidx,
        const float* __restrict__ emb,
        const float2* __restrict__ Wst,
        const float2* __restrict__ Wnt,
        const float2* __restrict__ Wet) {
    constexpr int D4 = DIN / 4;
    constexpr int D2 = DIN / 2;
    __shared__ __align__(16) float xs[DIN];
    __shared__ __align__(16) float ns[S * DIN];
    __shared__ __align__(16) float es[S * E_DIM];
    const int n = blockIdx.x;
    const int t = threadIdx.x;

    for (int i = t; i < D4; i += 128)
        ((float4*)xs)[i] = ((const float4*)x)[(long)n * D4 + i];
    for (int i = t; i < S * D4; i += 128)
        ((float4*)ns)[i] = ((const float4*)neigh)[(long)n * S * D4 + i];
    if (eidx) {
        for (int i = t; i < S * (E_DIM / 4); i += 128) {
            int s = i >> 3, c = i & 7;
            ((float4*)es)[i] = ((const float4*)emb)[(long)eidx[n * S + s] * 8 + c];
        }
    } else {
        for (int i = t; i < S * (E_DIM / 4); i += 128)
            ((float4*)es)[i] = ((const float4*)ed)[(long)n * S * (E_DIM / 4) + i];
    }
    __syncthreads();

    const int h  = t >> 4;
    const int cp = t & 15;
    // head bases in ulonglong2 units: [h][d2][16 col-pairs]
    const ulonglong2* wn2 = (const ulonglong2*)Wnt + (long)h * D2 * 16;
    const ulonglong2* ws2 = (const ulonglong2*)Wst + (long)h * D2 * 16;
    const ulonglong2* we2 = (const ulonglong2*)Wet + (long)h * (E_DIM / 2) * 16;

    const ulonglong2* xs2 = (const ulonglong2*)xs;
    const ulonglong2* ns2 = (const ulonglong2*)ns;
    const ulonglong2* es2 = (const ulonglong2*)es;

    u64 acc[S][2];
    u64 slf[2] = {0ull, 0ull};
#pragma unroll
    for (int s = 0; s < S; s++) { acc[s][0] = 0ull; acc[s][1] = 0ull; }

#pragma unroll 4
    for (int d4 = 0; d4 < D4; d4++) {
        ulonglong2 wnA = wn2[(2 * d4)     * 16 + cp];
        ulonglong2 wnB = wn2[(2 * d4 + 1) * 16 + cp];
        ulonglong2 wsA = ws2[(2 * d4)     * 16 + cp];
        ulonglong2 wsB = ws2[(2 * d4 + 1) * 16 + cp];
        ulonglong2 xv = xs2[d4];
        fma2(slf[0], xv.x, wsA.x);
        fma2(slf[1], xv.x, wsA.y);
        fma2(slf[0], xv.y, wsB.x);
        fma2(slf[1], xv.y, wsB.y);
#pragma unroll
        for (int s = 0; s < S; s++) {
            ulonglong2 nv = ns2[s * D4 + d4];
            fma2(acc[s][0], nv.x, wnA.x);
            fma2(acc[s][1], nv.x, wnA.y);
            fma2(acc[s][0], nv.y, wnB.x);
            fma2(acc[s][1], nv.y, wnB.y);
        }
    }
#pragma unroll
    for (int e4 = 0; e4 < E_DIM / 4; e4++) {
        ulonglong2 weA = we2[(2 * e4)     * 16 + cp];
        ulonglong2 weB = we2[(2 * e4 + 1) * 16 + cp];
#pragma unroll
        for (int s = 0; s < S; s++) {
            ulonglong2 ev = es2[s * (E_DIM / 4) + e4];
            fma2(acc[s][0], ev.x, weA.x);
            fma2(acc[s][1], ev.x, weA.y);
            fma2(acc[s][0], ev.y, weB.x);
            fma2(acc[s][1], ev.y, weB.y);
        }
    }

    float m0 = 0.f, m1 = 0.f;
#pragma unroll
    for (int s = 0; s < S; s++) {
        m0 += fmaxf(sum2(acc[s][0]), 0.f);
        m1 += fmaxf(sum2(acc[s][1]), 0.f);
    }
    out[(long)n * D_DIM + h * O_DIM + cp * 2 + 0] = fmaxf(sum2(slf[0]) + m0 * (1.0f / S), 0.f);
    out[(long)n * D_DIM + h * O_DIM + cp * 2 + 1] = fmaxf(sum2(slf[1]) + m1 * (1.0f / S), 0.f);
}

// ---------------- edge update: relu(concat(src, g1, ed0) @ Wedge) ----------------
// block = 16 rows, 256 threads: cp = t&15 -> cols 2cp, row r = t>>4.
__global__ __launch_bounds__(256) void edge_update_kernel(
        float* __restrict__ ed0u,
        const float* __restrict__ g0,
        const float* __restrict__ g1,
        const float* __restrict__ ed0,
        const float2* __restrict__ Wt) {
    __shared__ __align__(16) float cs[16 * KCAT];
    const int base = blockIdx.x * 16;
    const int t = threadIdx.x;
    for (int i = t; i < 16 * KCAT; i += 256) {
        int r = i / KCAT, k = i % KCAT;
        int row = base + r;
        float v;
        if (k < D_DIM)           v = g0[(long)(row / S) * D_DIM + k];
        else if (k < 2 * D_DIM)  v = g1[(long)row * D_DIM + (k - D_DIM)];
        else                     v = ed0[(long)row * E_DIM + (k - 2 * D_DIM)];
        cs[r * KCAT + k] = v;
    }
    __syncthreads();
    const int cp = t & 15;
    const int r  = t >> 4;
    const ulonglong2* cs2 = (const ulonglong2*)(cs + r * KCAT);
    const ulonglong2* w2  = (const ulonglong2*)Wt;   // [k2][16 col-pairs]
    u64 a0 = 0ull, a1 = 0ull;
#pragma unroll 4
    for (int k4 = 0; k4 < KCAT / 4; k4++) {
        ulonglong2 wA = w2[(2 * k4)     * 16 + cp];
        ulonglong2 wB = w2[(2 * k4 + 1) * 16 + cp];
        ulonglong2 cv = cs2[k4];
        fma2(a0, cv.x, wA.x);
        fma2(a1, cv.x, wA.y);
        fma2(a0, cv.y, wB.x);
        fma2(a1, cv.y, wB.y);
    }
    ed0u[(long)(base + r) * E_DIM + cp * 2 + 0] = fmaxf(sum2(a0), 0.f);
    ed0u[(long)(base + r) * E_DIM + cp * 2 + 1] = fmaxf(sum2(a1), 0.f);
}

// ---------------- head: attention over metapaths + normalize + fc ----------------
__global__ void head_kernel(float* __restrict__ dout,
                            const float* __restrict__ gout,
                            const float* __restrict__ Wa,
                            const float* __restrict__ va,
                            const float* __restrict__ Wfc,
                            const float* __restrict__ bfc) {
    const int b = blockIdx.x, t = threadIdx.x;
    __shared__ float red[128];
    __shared__ float scores[2];
    __shared__ float sw[2];
    __shared__ float anrm[D_DIM];
    __shared__ float invn;
    const float* g0 = gout + (long)b * D_DIM;
    const float* g1 = gout + (long)B * D_DIM + (long)b * D_DIM;

    {   // scores[mp] = tanh(g @ Wa) . va
        int mp = t >> 6, j = t & 63;
        const float* g = mp ? g1 : g0;
        float hv = 0.f;
        for (int d = 0; d < D_DIM; d++) hv += g[d] * Wa[d * 64 + j];
        red[t] = tanhf(hv) * va[j];
    }
    __syncthreads();
    if (t < 2) {
        float s = 0.f;
        for (int j = 0; j < 64; j++) s += red[t * 64 + j];
        scores[t] = s;
    }
    __syncthreads();
    if (t == 0) {
        float m = fmaxf(scores[0], scores[1]);
        float e0 = expf(scores[0] - m), e1 = expf(scores[1] - m);
        float inv = 1.f / (e0 + e1);
        sw[0] = e0 * inv; sw[1] = e1 * inv;
        dout[B * NCLS + b]     = sw[0];   // weights[0, b]
        dout[B * NCLS + B + b] = sw[1];   // weights[1, b]
    }
    __syncthreads();
    float ss = 0.f;
    for (int d = t; d < D_DIM; d += 128) {
        float a = sw[0] * g0[d] + sw[1] * g1[d];
        anrm[d] = a;
        ss += a * a;
    }
    red[t] = ss;
    __syncthreads();
    for (int off = 64; off > 0; off >>= 1) {
        if (t < off) red[t] += red[t + off];
        __syncthreads();
    }
    if (t == 0) invn = 1.f / fmaxf(sqrtf(red[0]), 1e-12f);
    __syncthreads();
    {   // logits: 8 cols x 16 partial threads
        int c = t >> 4, p = t & 15;
        float acc = 0.f;
        for (int d = p; d < D_DIM; d += 16) acc += anrm[d] * invn * Wfc[d * NCLS + c];
        for (int off = 8; off > 0; off >>= 1) acc += __shfl_down_sync(0xffffffffu, acc, off, 16);
        if (p == 0) dout[b * NCLS + c] = acc + bfc[c];
    }
}

// ---------------- launch ----------------
extern "C" void kernel_launch(void* const* d_in, const int* in_sizes, int n_in,
                              void* d_out, int out_size) {
    const int*   ids      = (const int*)d_in[0];
    const int*   n0m[2]   = {(const int*)d_in[1], (const int*)d_in[5]};
    const int*   e0m[2]   = {(const int*)d_in[2], (const int*)d_in[6]};
    const int*   n1m[2]   = {(const int*)d_in[3], (const int*)d_in[7]};
    const int*   e1m[2]   = {(const int*)d_in[4], (const int*)d_in[8]};
    const float* feats    = (const float*)d_in[9];
    const float* embm[2]  = {(const float*)d_in[10], (const float*)d_in[11]};
    const float* Wprep    = (const float*)d_in[12];
    const float* Ws0      = (const float*)d_in[13];
    const float* Wn0      = (const float*)d_in[14];
    const float* We0      = (const float*)d_in[15];
    const float* Ws1      = (const float*)d_in[16];
    const float* Wn1      = (const float*)d_in[17];
    const float* We1      = (const float*)d_in[18];
    const float* Wedge0   = (const float*)d_in[19];
    const float* Wa       = (const float*)d_in[20];
    const float* va       = (const float*)d_in[21];
    const float* Wfc      = (const float*)d_in[22];
    const float* bfc      = (const float*)d_in[23];
    float*       dout     = (float*)d_out;

    float *f0, *f1, *f2, *ed0, *g0, *g1, *ed0u, *gout;
    float2 *wprept, *wn0t, *ws0t, *we0t, *we1t, *wn1t, *ws1t, *wedget;
    cudaGetSymbolAddress((void**)&f0,     f0_buf);
    cudaGetSymbolAddress((void**)&f1,     f1_buf);
    cudaGetSymbolAddress((void**)&f2,     f2_buf);
    cudaGetSymbolAddress((void**)&ed0,    ed0_buf);
    cudaGetSymbolAddress((void**)&g0,     g0_buf);
    cudaGetSymbolAddress((void**)&g1,     g1_buf);
    cudaGetSymbolAddress((void**)&ed0u,   ed0u_buf);
    cudaGetSymbolAddress((void**)&gout,   gout_buf);
    cudaGetSymbolAddress((void**)&wprept, wprept_buf);
    cudaGetSymbolAddress((void**)&wn0t,   wn0t_buf);
    cudaGetSymbolAddress((void**)&ws0t,   ws0t_buf);
    cudaGetSymbolAddress((void**)&we0t,   we0t_buf);
    cudaGetSymbolAddress((void**)&we1t,   we1t_buf);
    cudaGetSymbolAddress((void**)&wn1t,   wn1t_buf);
    cudaGetSymbolAddress((void**)&ws1t,   ws1t_buf);
    cudaGetSymbolAddress((void**)&wedget, wedget_buf);

    // ---- weight pair-packs (cheap, once per launch); totals in float2 elems ----
    {
        int n;
        n = 64 * 128;               wtrans_kernel<<<(n + 255) / 256, 256>>>(wprept, Wprep, 128, 128, n);
        n = 16 * 64 * 32;           wtrans_kernel<<<(n + 255) / 256, 256>>>(wn0t, Wn0, 128, 32, n);
        n = 16 * 64 * 32;           wtrans_kernel<<<(n + 255) / 256, 256>>>(ws0t, Ws0, 128, 32, n);
        n = 16 * 16 * 32;           wtrans_kernel<<<(n + 255) / 256, 256>>>(we0t, We0, 32, 32, n);
        n = 16 * 16 * 32;           wtrans_kernel<<<(n + 255) / 256, 256>>>(we1t, We1, 32, 32, n);
        n = 16 * 128 * 32;          wtrans_kernel<<<(n + 255) / 256, 256>>>(wn1t, Wn1, 256, 32, n);
        n = 16 * 128 * 32;          wtrans_kernel<<<(n + 255) / 256, 256>>>(ws1t, Ws1, 256, 32, n);
        n = 2 * 272 * 32;           wtrans_kernel<<<(n + 255) / 256, 256>>>(wedget, Wedge0, KCAT, 32, n);
    }

    // f0 = prep(ids): shared across metapaths (Wprep shared)
    prep_kernel<<<B / 32, 256>>>(f0, feats, ids, wprept);

    for (int mp = 0; mp < NMP; mp++) {
        const float2* wn0m = wn0t + (long)mp * H_NUM * 64 * 32;
        const float2* ws0m = ws0t + (long)mp * H_NUM * 64 * 32;
        const float2* we0m = we0t + (long)mp * H_NUM * 16 * 32;
        const float2* we1m = we1t + (long)mp * H_NUM * 16 * 32;
        const float2* wn1m = wn1t + (long)mp * H_NUM * 128 * 32;
        const float2* ws1m = ws1t + (long)mp * H_NUM * 128 * 32;
        const float2* wegm = wedget + (long)mp * 272 * 32;

        prep_kernel<<<(B * S) / 32, 256>>>(f1, feats, n0m[mp], wprept);
        prep_kernel<<<(B * S * S) / 32, 256>>>(f2, feats, n1m[mp], wprept);

        gather_edge_kernel<<<(B * S * 8 + 255) / 256, 256>>>(ed0, embm[mp], e0m[mp], B * S);

        // g0: edges from ed0 buffer; g1: edges gathered in-kernel from emb (fused)
        agg_kernel<128><<<B, 128>>>(g0, f0, f1, ed0, (const int*)nullptr, (const float*)nullptr,
                                    ws0m, wn0m, we0m);
        agg_kernel<128><<<B * S, 128>>>(g1, f1, f2, (const float*)nullptr, e1m[mp], embm[mp],
                                        ws0m, wn0m, we0m);

        edge_update_kernel<<<(B * S) / 16, 256>>>(ed0u, g0, g1, ed0, wegm);

        agg_kernel<256><<<B, 128>>>(gout + (long)mp * B * D_DIM, g0, g1, ed0u,
                                    (const int*)nullptr, (const float*)nullptr,
                                    ws1m, wn1m, we1m);
    }

    head_kernel<<<B, 128>>>(dout, gout, Wa, va, Wfc, bfc);
}